// round 16
// baseline (speedup 1.0000x reference)
#include <cuda_runtime.h>
#include <cuda_fp16.h>
#include <cstdint>

// Problem constants
#define BATCH 2048
#define SEQ   64
#define HEADS 8
#define M_ROWS (BATCH * SEQ)                  // 131072
#define OUT_ELEMS ((long long)M_ROWS * 512)   // 67108864

// Scratch (allocation-free rule: __device__ globals) — fp16, proven R14 set
__device__ __align__(16) __half g_q[(size_t)M_ROWS * 512];
__device__ __align__(16) __half g_k[(size_t)M_ROWS * 512];
__device__ __align__(16) __half g_v[(size_t)M_ROWS * 512];
__device__ __align__(16) __half g_att[(size_t)M_ROWS * 512];

// ---------------------------------------------------------------------------
// fp16 helpers
// ---------------------------------------------------------------------------
__device__ __forceinline__ uint32_t pack_h2(float lo, float hi) {
    // d.lo = second PTX source, d.hi = first
    uint32_t r;
    asm("cvt.rn.f16x2.f32 %0, %1, %2;" : "=r"(r) : "f"(hi), "f"(lo));
    return r;
}

__device__ __forceinline__ void mma_f16(float c[4], const uint32_t a[4],
                                        uint32_t b0, uint32_t b1) {
    asm volatile(
        "mma.sync.aligned.m16n8k16.row.col.f32.f16.f16.f32 "
        "{%0,%1,%2,%3}, {%4,%5,%6,%7}, {%8,%9}, {%0,%1,%2,%3};\n"
        : "+f"(c[0]), "+f"(c[1]), "+f"(c[2]), "+f"(c[3])
        : "r"(a[0]), "r"(a[1]), "r"(a[2]), "r"(a[3]), "r"(b0), "r"(b1));
}

// ---------------------------------------------------------------------------
// GEMM: C[M,512] = A[M,512] * W[512,512] + bias   (fp16 mma.sync, fp32 accum)
// Delta vs R14 (single change): 128 threads = 4 warps in 2m x 2n grid,
// warp tile 64x64 (was 8 warps of 32x64). Same 128x128 CTA tile, same smem
// layouts (A pair-interleaved pitch 24; B word-pairs pitch 136), same k-order
// per output (bit-identical results). B fragment traffic halves.
// mode 0: A = X (fp32); bx: mat=bx>>2 -> fp16 g_q/g_k/g_v; n0=(bx&3)*128
// mode 1: A = g_att (fp16), W = W0, C = Cout (fp32)
// ---------------------------------------------------------------------------
#define APITCH 24
#define BPITCH 136
#define A_WORDS (128 * APITCH)   // 3072
#define B_WORDS (16 * BPITCH)    // 2176

__global__ __launch_bounds__(128, 2)
void gemm_f16(const float* __restrict__ X, float* __restrict__ Cout,
              const float* __restrict__ W0, const float* __restrict__ W1,
              const float* __restrict__ W2,
              const float* __restrict__ bias0, const float* __restrict__ bias1,
              const float* __restrict__ bias2, int mode)
{
    __shared__ uint32_t Asm[2][A_WORDS];
    __shared__ uint32_t Bsm[2][B_WORDS];

    const int t  = threadIdx.x;
    const int m0 = blockIdx.y * 128;

    const float* W; const float* bias; __half* Ch = nullptr; float* Cf = nullptr; int n0;
    if (mode == 0) {
        const int mat = blockIdx.x >> 2;
        n0 = (blockIdx.x & 3) * 128;
        W    = (mat == 0) ? W0 : (mat == 1) ? W1 : W2;
        bias = (mat == 0) ? bias0 : (mat == 1) ? bias1 : bias2;
        Ch   = (mat == 0) ? g_q : (mat == 1) ? g_k : g_v;
    } else {
        n0 = blockIdx.x * 128;
        W = W0; bias = bias0; Cf = Cout;
    }

    // staging maps (128 threads: each thread stages one full A row and one
    // full B kkr-row = 16 words each)
    const int kkr = t >> 3;           // 0..15
    const int nc  = (t & 7) * 16;     // word col 0..112

    const float*  Apf = X     + (size_t)(m0 + t) * 512;   // mode 0 (fp32)
    const __half* Aph = g_att + (size_t)(m0 + t) * 512;   // mode 1 (fp16)
    const float* Bp0 = W + (size_t)(2 * kkr)     * 512 + n0 + nc;
    const float* Bp1 = W + (size_t)(2 * kkr + 1) * 512 + n0 + nc;

    // warp mapping: 2 (m) x 2 (n), warp tile 64x64
    const int w = t >> 5, lane = t & 31;
    const int gid = lane >> 2, tig = lane & 3;
    const int wm = (w & 1) * 64;
    const int wn = (w >> 1) * 64;

    float acc[4][8][4];
#pragma unroll
    for (int mi = 0; mi < 4; mi++)
#pragma unroll
        for (int nj = 0; nj < 8; nj++)
#pragma unroll
            for (int c = 0; c < 4; c++) acc[mi][nj][c] = 0.0f;

    float4 ra[8];          // mode-0 A prefetch (full row chunk, 32 floats)
    uint4  ua[4];          // mode-1 A prefetch (16 packed words)
    float4 rbl[4], rbh[4]; // B prefetch (two fp32 rows x 16 cols)

    // helper lambdas for staging (identical word algebra to R14)
    auto stage_A = [&](int buf) {
        uint32_t* d = &Asm[buf][t * APITCH];
        if (mode == 0) {
#pragma unroll
            for (int half = 0; half < 2; half++) {
                uint32_t wv[8];
#pragma unroll
                for (int j = 0; j < 4; j++) {
                    const float4 f = ra[half * 4 + j];
                    wv[2 * j]     = pack_h2(f.x, f.y);
                    wv[2 * j + 1] = pack_h2(f.z, f.w);
                }
                *(uint4*)(d + half * 8)     = make_uint4(wv[0], wv[4], wv[1], wv[5]);
                *(uint4*)(d + half * 8 + 4) = make_uint4(wv[2], wv[6], wv[3], wv[7]);
            }
        } else {
            *(uint4*)(d)      = make_uint4(ua[0].x, ua[1].x, ua[0].y, ua[1].y);
            *(uint4*)(d + 4)  = make_uint4(ua[0].z, ua[1].z, ua[0].w, ua[1].w);
            *(uint4*)(d + 8)  = make_uint4(ua[2].x, ua[3].x, ua[2].y, ua[3].y);
            *(uint4*)(d + 12) = make_uint4(ua[2].z, ua[3].z, ua[2].w, ua[3].w);
        }
    };
    auto stage_B = [&](int buf) {
        uint32_t* d = &Bsm[buf][kkr * BPITCH + nc];
#pragma unroll
        for (int j = 0; j < 4; j++) {
            const float* lo = (const float*)&rbl[j];
            const float* hi = (const float*)&rbh[j];
            *(uint4*)(d + 4 * j) = make_uint4(pack_h2(lo[0], hi[0]), pack_h2(lo[1], hi[1]),
                                              pack_h2(lo[2], hi[2]), pack_h2(lo[3], hi[3]));
        }
    };
    auto load_stage = [&](int kt) {
        if (mode == 0) {
            const float* s = Apf + kt * 32;
#pragma unroll
            for (int j = 0; j < 8; j++) ra[j] = *(const float4*)(s + 4 * j);
        } else {
            const __half* s = Aph + kt * 32;
#pragma unroll
            for (int j = 0; j < 4; j++) ua[j] = *(const uint4*)(s + 8 * j);
        }
        const float* b0 = Bp0 + (size_t)(kt * 32) * 512;
        const float* b1 = Bp1 + (size_t)(kt * 32) * 512;
#pragma unroll
        for (int j = 0; j < 4; j++) {
            rbl[j] = *(const float4*)(b0 + 4 * j);
            rbh[j] = *(const float4*)(b1 + 4 * j);
        }
    };

    // prologue: stage kt = 0 into buf 0
    load_stage(0);
    stage_A(0);
    stage_B(0);
    __syncthreads();

    for (int kt = 0; kt < 16; kt++) {
        const int cb = kt & 1;
        if (kt < 15) load_stage(kt + 1);

        const uint32_t* as = Asm[cb];
        const uint32_t* bs = Bsm[cb];
#pragma unroll
        for (int ks = 0; ks < 2; ks++) {
            const int kb = ks * 8;
            const int kw = kb + tig * 2;
            uint32_t a[4][4];
#pragma unroll
            for (int mi = 0; mi < 4; mi++) {
                const int r = wm + mi * 16 + gid;
                const uint2 lo = *(const uint2*)(as + r * APITCH + kw);
                const uint2 hi = *(const uint2*)(as + (r + 8) * APITCH + kw);
                a[mi][0] = lo.x; a[mi][1] = hi.x; a[mi][2] = lo.y; a[mi][3] = hi.y;
            }
#pragma unroll
            for (int nj = 0; nj < 8; nj++) {
                const int c = wn + nj * 8 + gid;
                const uint32_t b0 = bs[(kb + tig) * BPITCH + c];
                const uint32_t b1 = bs[(kb + 4 + tig) * BPITCH + c];
#pragma unroll
                for (int mi = 0; mi < 4; mi++)
                    mma_f16(acc[mi][nj], a[mi], b0, b1);
            }
        }

        if (kt < 15) {
            const int nb = cb ^ 1;
            stage_A(nb);
            stage_B(nb);
        }
        __syncthreads();
    }

    // epilogue: bias; mode 0 -> half2 stores, mode 1 -> float2 stores
#pragma unroll
    for (int mi = 0; mi < 4; mi++) {
#pragma unroll
        for (int nj = 0; nj < 8; nj++) {
            const int row = m0 + wm + mi * 16 + gid;
            const int col = n0 + wn + nj * 8 + tig * 2;
            const float2 bv = *(const float2*)(bias + col);
            const float v0 = acc[mi][nj][0] + bv.x, v1 = acc[mi][nj][1] + bv.y;
            const float v2 = acc[mi][nj][2] + bv.x, v3 = acc[mi][nj][3] + bv.y;
            if (mode == 0) {
                *(uint32_t*)(Ch + (size_t)row * 512 + col)       = pack_h2(v0, v1);
                *(uint32_t*)(Ch + (size_t)(row + 8) * 512 + col) = pack_h2(v2, v3);
            } else {
                *(float2*)(Cf + (size_t)row * 512 + col)       = make_float2(v0, v1);
                *(float2*)(Cf + (size_t)(row + 8) * 512 + col) = make_float2(v2, v3);
            }
        }
    }
}

// ---------------------------------------------------------------------------
// Attention (byte-identical to R14 pass): mma core, fp16 word-shuffle staging
// ---------------------------------------------------------------------------
#define QPITCH 40
#define KVPITCH 72

__global__ __launch_bounds__(128)
void attn_mma(const float* __restrict__ mask)
{
    __shared__ uint32_t sQ[64 * QPITCH];
    __shared__ uint32_t sK[32 * KVPITCH];
    __shared__ uint32_t sV[32 * KVPITCH];
    __shared__ float    sM[64 * 68];

    const int b = blockIdx.y;
    const int h = blockIdx.x;
    const int t = threadIdx.x;
    const size_t base = ((size_t)b * 64) * 512 + (size_t)h * 64;

    // ---- stage Q (A-interleave; direct word copies) ----
    {
        const int row = t >> 1, ch = t & 1;
        const __half* src = g_q + base + (size_t)row * 512 + ch * 32;
        uint32_t* dq = sQ + row * QPITCH + ch * 16;
#pragma unroll
        for (int g = 0; g < 2; g++) {
            uint4 u0 = *(const uint4*)(src + g * 16);
            uint4 u1 = *(const uint4*)(src + g * 16 + 8);
            *(uint4*)(dq + g * 8)     = make_uint4(u0.x, u1.x, u0.y, u1.y);
            *(uint4*)(dq + g * 8 + 4) = make_uint4(u0.z, u1.z, u0.w, u1.w);
        }
    }
    // ---- stage K (word transpose-scatter) ----
    {
        const int j = t >> 1, dh = (t & 1) * 32;
        const __half* src = g_k + base + (size_t)j * 512 + dh;
        uint32_t wds[16];
#pragma unroll
        for (int g = 0; g < 4; g++) *(uint4*)&wds[4 * g] = *(const uint4*)(src + 8 * g);
        const int kk0 = dh >> 1;
#pragma unroll
        for (int p = 0; p < 16; p++)
            sK[(kk0 + p) * KVPITCH + j] = wds[p];
    }
    // ---- stage V (lo/hi merge of two rows via byte_perm) ----
    {
        const int kk = t >> 2, nb = (t & 3) * 16;
        const __half* vlo = g_v + base + (size_t)(2 * kk) * 512 + nb;
        const __half* vhi = vlo + 512;
        uint32_t L[8], H[8];
        *(uint4*)&L[0] = *(const uint4*)(vlo);
        *(uint4*)&L[4] = *(const uint4*)(vlo + 8);
        *(uint4*)&H[0] = *(const uint4*)(vhi);
        *(uint4*)&H[4] = *(const uint4*)(vhi + 8);
        uint32_t* dv = sV + kk * KVPITCH + nb;
        uint32_t o[16];
#pragma unroll
        for (int j = 0; j < 8; j++) {
            o[2 * j]     = __byte_perm(L[j], H[j], 0x5410);
            o[2 * j + 1] = __byte_perm(L[j], H[j], 0x7632);
        }
#pragma unroll
        for (int g = 0; g < 4; g++) *(uint4*)(dv + 4 * g) = *(uint4*)&o[4 * g];
    }
    // ---- stage mask tile ----
    {
        const int row = t >> 1, cm = (t & 1) * 32;
        const float* src = mask + (size_t)b * 4096 + row * 64 + cm;
        float* dm = sM + row * 68 + cm;
#pragma unroll
        for (int g = 0; g < 8; g++) *(float4*)(dm + 4 * g) = *(const float4*)(src + 4 * g);
    }
    __syncthreads();

    const int wq = t >> 5, lane = t & 31;
    const int gid = lane >> 2, tig = lane & 3;
    const int r0 = wq * 16 + gid;

    // ---- S = Q K^T ----
    float sacc[8][4];
#pragma unroll
    for (int nj = 0; nj < 8; nj++)
#pragma unroll
        for (int c = 0; c < 4; c++) sacc[nj][c] = 0.0f;

#pragma unroll
    for (int KS = 0; KS < 4; KS++) {
        const int kw = KS * 8 + tig * 2;
        const uint2 lo = *(const uint2*)(sQ + r0 * QPITCH + kw);
        const uint2 hi = *(const uint2*)(sQ + (r0 + 8) * QPITCH + kw);
        uint32_t a[4] = { lo.x, hi.x, lo.y, hi.y };
#pragma unroll
        for (int nj = 0; nj < 8; nj++) {
            const int c = nj * 8 + gid;
            const uint32_t b0 = sK[(KS * 8 + tig) * KVPITCH + c];
            const uint32_t b1 = sK[(KS * 8 + 4 + tig) * KVPITCH + c];
            mma_f16(sacc[nj], a, b0, b1);
        }
    }

    // ---- masked softmax ----
    float mx0 = -1e30f, mx1 = -1e30f;
#pragma unroll
    for (int nj = 0; nj < 8; nj++) {
        const float2 m0 = *(const float2*)(sM + r0 * 68 + nj * 8 + 2 * tig);
        const float2 m1 = *(const float2*)(sM + (r0 + 8) * 68 + nj * 8 + 2 * tig);
        sacc[nj][0] = sacc[nj][0] * 0.125f + __logf(m0.x + 1e-9f);
        sacc[nj][1] = sacc[nj][1] * 0.125f + __logf(m0.y + 1e-9f);
        sacc[nj][2] = sacc[nj][2] * 0.125f + __logf(m1.x + 1e-9f);
        sacc[nj][3] = sacc[nj][3] * 0.125f + __logf(m1.y + 1e-9f);
        mx0 = fmaxf(mx0, fmaxf(sacc[nj][0], sacc[nj][1]));
        mx1 = fmaxf(mx1, fmaxf(sacc[nj][2], sacc[nj][3]));
    }
    mx0 = fmaxf(mx0, __shfl_xor_sync(0xffffffffu, mx0, 1));
    mx0 = fmaxf(mx0, __shfl_xor_sync(0xffffffffu, mx0, 2));
    mx1 = fmaxf(mx1, __shfl_xor_sync(0xffffffffu, mx1, 1));
    mx1 = fmaxf(mx1, __shfl_xor_sync(0xffffffffu, mx1, 2));

    float sum0 = 0.0f, sum1 = 0.0f;
#pragma unroll
    for (int nj = 0; nj < 8; nj++) {
        sacc[nj][0] = __expf(sacc[nj][0] - mx0);
        sacc[nj][1] = __expf(sacc[nj][1] - mx0);
        sacc[nj][2] = __expf(sacc[nj][2] - mx1);
        sacc[nj][3] = __expf(sacc[nj][3] - mx1);
        sum0 += sacc[nj][0] + sacc[nj][1];
        sum1 += sacc[nj][2] + sacc[nj][3];
    }
    sum0 += __shfl_xor_sync(0xffffffffu, sum0, 1);
    sum0 += __shfl_xor_sync(0xffffffffu, sum0, 2);
    sum1 += __shfl_xor_sync(0xffffffffu, sum1, 1);
    sum1 += __shfl_xor_sync(0xffffffffu, sum1, 2);
    const float inv0 = 1.0f / sum0, inv1 = 1.0f / sum1;
#pragma unroll
    for (int nj = 0; nj < 8; nj++) {
        sacc[nj][0] *= inv0; sacc[nj][1] *= inv0;
        sacc[nj][2] *= inv1; sacc[nj][3] *= inv1;
    }

    // ---- O = P V ----
    float oacc[8][4];
#pragma unroll
    for (int nd = 0; nd < 8; nd++)
#pragma unroll
        for (int c = 0; c < 4; c++) oacc[nd][c] = 0.0f;

#pragma unroll
    for (int JS = 0; JS < 4; JS++) {
        uint32_t a[4];
        a[0] = pack_h2(sacc[2 * JS][0],     sacc[2 * JS][1]);
        a[1] = pack_h2(sacc[2 * JS][2],     sacc[2 * JS][3]);
        a[2] = pack_h2(sacc[2 * JS + 1][0], sacc[2 * JS + 1][1]);
        a[3] = pack_h2(sacc[2 * JS + 1][2], sacc[2 * JS + 1][3]);
#pragma unroll
        for (int nd = 0; nd < 8; nd++) {
            const int c = nd * 8 + gid;
            const uint32_t b0 = sV[(JS * 8 + tig) * KVPITCH + c];
            const uint32_t b1 = sV[(JS * 8 + 4 + tig) * KVPITCH + c];
            mma_f16(oacc[nd], a, b0, b1);
        }
    }

    // ---- epilogue: half2 stores into g_att ----
    const int grow = b * 64 + r0;
#pragma unroll
    for (int nd = 0; nd < 8; nd++) {
        const int col = h * 64 + nd * 8 + tig * 2;
        *(uint32_t*)(g_att + (size_t)grow * 512 + col) =
            pack_h2(oacc[nd][0], oacc[nd][1]);
        *(uint32_t*)(g_att + (size_t)(grow + 8) * 512 + col) =
            pack_h2(oacc[nd][2], oacc[nd][3]);
    }
}

__global__ void tail_zero(float* __restrict__ out, long long start, long long total)
{
    long long i = start + (long long)blockIdx.x * blockDim.x + threadIdx.x;
    if (i < total) out[i] = 0.0f;
}

// ---------------------------------------------------------------------------
extern "C" void kernel_launch(void* const* d_in, const int* in_sizes, int n_in,
                              void* d_out, int out_size)
{
    const float* x    = (const float*)d_in[0];
    const float* mask = (const float*)d_in[1];
    const float* Wq   = (const float*)d_in[2];
    const float* bq   = (const float*)d_in[3];
    const float* Wk   = (const float*)d_in[4];
    const float* bk   = (const float*)d_in[5];
    const float* Wv   = (const float*)d_in[6];
    const float* bv   = (const float*)d_in[7];
    const float* Wo   = (const float*)d_in[8];
    const float* bo   = (const float*)d_in[9];
    float* out = (float*)d_out;

    // 0) Tail first (ccd_loss scalar / padding)
    long long tail = (long long)out_size - OUT_ELEMS;
    if (tail > 0) {
        int blocks = (int)((tail + 255) / 256);
        tail_zero<<<blocks, 256>>>(out, OUT_ELEMS, (long long)out_size);
    }

    // 1) Fused QKV projections (grid.x = 12 -> {q,k,v} x 4 n-tiles of 128)
    gemm_f16<<<dim3(12, 1024), 128>>>(x, nullptr, Wq, Wk, Wv, bq, bk, bv, 0);

    // 2) Channel-masked attention (tensor-core)
    attn_mma<<<dim3(HEADS, BATCH), 128>>>(mask);

    // 3) Output projection (grid.x = 4)
    gemm_f16<<<dim3(4, 1024), 128>>>(nullptr, out, Wo, Wo, Wo, bo, bo, bo, 1);
}

// round 17
// speedup vs baseline: 1.1770x; 1.1770x over previous
#include <cuda_runtime.h>
#include <cuda_fp16.h>
#include <cstdint>

// Problem constants
#define BATCH 2048
#define SEQ   64
#define HEADS 8
#define M_ROWS (BATCH * SEQ)                  // 131072
#define OUT_ELEMS ((long long)M_ROWS * 512)   // 67108864

// Scratch (allocation-free rule: __device__ globals) — fp16, proven R14 set
__device__ __align__(16) __half g_q[(size_t)M_ROWS * 512];
__device__ __align__(16) __half g_k[(size_t)M_ROWS * 512];
__device__ __align__(16) __half g_v[(size_t)M_ROWS * 512];
__device__ __align__(16) __half g_att[(size_t)M_ROWS * 512];

// ---------------------------------------------------------------------------
// fp16 helpers
// ---------------------------------------------------------------------------
__device__ __forceinline__ uint32_t pack_h2(float lo, float hi) {
    // d.lo = second PTX source, d.hi = first
    uint32_t r;
    asm("cvt.rn.f16x2.f32 %0, %1, %2;" : "=r"(r) : "f"(hi), "f"(lo));
    return r;
}

__device__ __forceinline__ void mma_f16(float c[4], const uint32_t a[4],
                                        uint32_t b0, uint32_t b1) {
    asm volatile(
        "mma.sync.aligned.m16n8k16.row.col.f32.f16.f16.f32 "
        "{%0,%1,%2,%3}, {%4,%5,%6,%7}, {%8,%9}, {%0,%1,%2,%3};\n"
        : "+f"(c[0]), "+f"(c[1]), "+f"(c[2]), "+f"(c[3])
        : "r"(a[0]), "r"(a[1]), "r"(a[2]), "r"(a[3]), "r"(b0), "r"(b1));
}

// ---------------------------------------------------------------------------
// GEMM common geometry: CTA tile 128(m) x 256(n) x K32, 512 threads =
// 16 warps in 4m x 4n grid, warp tile 32x64 (R14-proven 64-reg accumulator).
// Smem (dynamic): A[2][128][24w] pair-interleaved, B[2][16kk][264w] word-pairs.
// Double-buffered, one __syncthreads per k-step. Same k-order as R14
// (bit-identical numerics).
// ---------------------------------------------------------------------------
#define APITCH 24
#define BPITCH 264
#define A_WORDS (128 * APITCH)   // 3072
#define B_WORDS (16 * BPITCH)    // 4224
#define SMEM_WORDS (2 * A_WORDS + 2 * B_WORDS)        // 14592
#define GEMM_DSMEM (SMEM_WORDS * 4)                   // 58368

// ---- mode-0: C = x @ W{q,k,v} + b -> fp16 g_q/g_k/g_v ---------------------
__global__ __launch_bounds__(512, 1)
void gemm_qkv(const float* __restrict__ X,
              const float* __restrict__ W0, const float* __restrict__ W1,
              const float* __restrict__ W2,
              const float* __restrict__ bias0, const float* __restrict__ bias1,
              const float* __restrict__ bias2)
{
    extern __shared__ uint32_t smw[];
    uint32_t* const Abuf[2] = { smw, smw + A_WORDS };
    uint32_t* const Bbuf[2] = { smw + 2 * A_WORDS, smw + 2 * A_WORDS + B_WORDS };

    const int t  = threadIdx.x;
    const int m0 = blockIdx.y * 128;
    const int mat = blockIdx.x >> 1;
    const int n0  = (blockIdx.x & 1) * 256;
    const float* W    = (mat == 0) ? W0 : (mat == 1) ? W1 : W2;
    const float* bias = (mat == 0) ? bias0 : (mat == 1) ? bias1 : bias2;
    __half* C = (mat == 0) ? g_q : (mat == 1) ? g_k : g_v;

    // A staging: thread -> (row = t>>2, q4 = t&3 -> h = q4>>1, sub = q4&1)
    const int arow = t >> 2;
    const int h    = (t >> 1) & 1;
    const int sub  = t & 1;
    const float* Ap = X + (size_t)(m0 + arow) * 512 + h * 16 + sub * 4;
    const int adst = arow * APITCH + h * 8 + 4 * sub;

    // B staging: thread -> (kkr = t>>5, nc = (t&31)*8)
    const int kkr = t >> 5;
    const int nc  = (t & 31) * 8;
    const float* Bp0 = W + (size_t)(2 * kkr)     * 512 + n0 + nc;
    const float* Bp1 = W + (size_t)(2 * kkr + 1) * 512 + n0 + nc;
    const int bdst = kkr * BPITCH + nc;

    // warp mapping: 4m x 4n, warp tile 32x64
    const int w = t >> 5, lane = t & 31;
    const int gid = lane >> 2, tig = lane & 3;
    const int wm = (w & 3) * 32;
    const int wn = (w >> 2) * 64;

    float acc[2][8][4];
#pragma unroll
    for (int mi = 0; mi < 2; mi++)
#pragma unroll
        for (int nj = 0; nj < 8; nj++)
#pragma unroll
            for (int c = 0; c < 4; c++) acc[mi][nj][c] = 0.0f;

    float4 ra0, ra1, rbl[2], rbh[2];
    auto load_stage = [&](int kt) {
        const float* s = Ap + kt * 32;
        ra0 = *(const float4*)(s);
        ra1 = *(const float4*)(s + 8);
        const float* b0 = Bp0 + (size_t)(kt * 32) * 512;
        const float* b1 = Bp1 + (size_t)(kt * 32) * 512;
#pragma unroll
        for (int j = 0; j < 2; j++) {
            rbl[j] = *(const float4*)(b0 + 4 * j);
            rbh[j] = *(const float4*)(b1 + 4 * j);
        }
    };
    auto stage = [&](int buf) {
        // pairs: ra0 = q{2s,2s+1}, ra1 = q{4+2s,4+2s+1} -> pos 4s..4s+3
        *(uint4*)&Abuf[buf][adst] =
            make_uint4(pack_h2(ra0.x, ra0.y), pack_h2(ra1.x, ra1.y),
                       pack_h2(ra0.z, ra0.w), pack_h2(ra1.z, ra1.w));
#pragma unroll
        for (int j = 0; j < 2; j++) {
            const float* lo = (const float*)&rbl[j];
            const float* hi = (const float*)&rbh[j];
            *(uint4*)&Bbuf[buf][bdst + 4 * j] =
                make_uint4(pack_h2(lo[0], hi[0]), pack_h2(lo[1], hi[1]),
                           pack_h2(lo[2], hi[2]), pack_h2(lo[3], hi[3]));
        }
    };

    load_stage(0);
    stage(0);
    __syncthreads();

    for (int kt = 0; kt < 16; kt++) {
        const int cb = kt & 1;
        if (kt < 15) load_stage(kt + 1);

        const uint32_t* as = Abuf[cb];
        const uint32_t* bs = Bbuf[cb];
#pragma unroll
        for (int ks = 0; ks < 2; ks++) {
            const int kb = ks * 8;
            const int kw = kb + tig * 2;
            uint32_t a[2][4];
#pragma unroll
            for (int mi = 0; mi < 2; mi++) {
                const int r = wm + mi * 16 + gid;
                const uint2 lo = *(const uint2*)(as + r * APITCH + kw);
                const uint2 hi = *(const uint2*)(as + (r + 8) * APITCH + kw);
                a[mi][0] = lo.x; a[mi][1] = hi.x; a[mi][2] = lo.y; a[mi][3] = hi.y;
            }
#pragma unroll
            for (int nj = 0; nj < 8; nj++) {
                const int c = wn + nj * 8 + gid;
                const uint32_t b0 = bs[(kb + tig) * BPITCH + c];
                const uint32_t b1 = bs[(kb + 4 + tig) * BPITCH + c];
                mma_f16(acc[0][nj], a[0], b0, b1);
                mma_f16(acc[1][nj], a[1], b0, b1);
            }
        }

        if (kt < 15) stage(cb ^ 1);
        __syncthreads();
    }

#pragma unroll
    for (int mi = 0; mi < 2; mi++) {
#pragma unroll
        for (int nj = 0; nj < 8; nj++) {
            const int row = m0 + wm + mi * 16 + gid;
            const int col = n0 + wn + nj * 8 + tig * 2;
            const float2 bv = *(const float2*)(bias + col);
            *(uint32_t*)(C + (size_t)row * 512 + col) =
                pack_h2(acc[mi][nj][0] + bv.x, acc[mi][nj][1] + bv.y);
            *(uint32_t*)(C + (size_t)(row + 8) * 512 + col) =
                pack_h2(acc[mi][nj][2] + bv.x, acc[mi][nj][3] + bv.y);
        }
    }
}

// ---- mode-1: out = g_att @ Wo + bo (fp16 A, fp32 out) ---------------------
__global__ __launch_bounds__(512, 1)
void gemm_out(float* __restrict__ Cout, const float* __restrict__ W,
              const float* __restrict__ bias)
{
    extern __shared__ uint32_t smw[];
    uint32_t* const Abuf[2] = { smw, smw + A_WORDS };
    uint32_t* const Bbuf[2] = { smw + 2 * A_WORDS, smw + 2 * A_WORDS + B_WORDS };

    const int t  = threadIdx.x;
    const int m0 = blockIdx.y * 128;
    const int n0 = blockIdx.x * 256;

    const int arow = t >> 2;
    const int h    = (t >> 1) & 1;
    const int sub  = t & 1;
    // fp16 source: uint2 word-pairs at pair indices (8h+2s) and (8h+4+2s)
    const __half* Ap = g_att + (size_t)(m0 + arow) * 512 + 16 * h + 4 * sub;
    const int adst = arow * APITCH + h * 8 + 4 * sub;

    const int kkr = t >> 5;
    const int nc  = (t & 31) * 8;
    const float* Bp0 = W + (size_t)(2 * kkr)     * 512 + n0 + nc;
    const float* Bp1 = W + (size_t)(2 * kkr + 1) * 512 + n0 + nc;
    const int bdst = kkr * BPITCH + nc;

    const int w = t >> 5, lane = t & 31;
    const int gid = lane >> 2, tig = lane & 3;
    const int wm = (w & 3) * 32;
    const int wn = (w >> 2) * 64;

    float acc[2][8][4];
#pragma unroll
    for (int mi = 0; mi < 2; mi++)
#pragma unroll
        for (int nj = 0; nj < 8; nj++)
#pragma unroll
            for (int c = 0; c < 4; c++) acc[mi][nj][c] = 0.0f;

    uint2 u01, u45;
    float4 rbl[2], rbh[2];
    auto load_stage = [&](int kt) {
        const __half* s = Ap + kt * 32;
        u01 = *(const uint2*)(s);        // words: pairs (8h+2s), (8h+2s+1)
        u45 = *(const uint2*)(s + 8);    // words: pairs (8h+4+2s), (+1)
        const float* b0 = Bp0 + (size_t)(kt * 32) * 512;
        const float* b1 = Bp1 + (size_t)(kt * 32) * 512;
#pragma unroll
        for (int j = 0; j < 2; j++) {
            rbl[j] = *(const float4*)(b0 + 4 * j);
            rbh[j] = *(const float4*)(b1 + 4 * j);
        }
    };
    auto stage = [&](int buf) {
        *(uint4*)&Abuf[buf][adst] = make_uint4(u01.x, u45.x, u01.y, u45.y);
#pragma unroll
        for (int j = 0; j < 2; j++) {
            const float* lo = (const float*)&rbl[j];
            const float* hi = (const float*)&rbh[j];
            *(uint4*)&Bbuf[buf][bdst + 4 * j] =
                make_uint4(pack_h2(lo[0], hi[0]), pack_h2(lo[1], hi[1]),
                           pack_h2(lo[2], hi[2]), pack_h2(lo[3], hi[3]));
        }
    };

    load_stage(0);
    stage(0);
    __syncthreads();

    for (int kt = 0; kt < 16; kt++) {
        const int cb = kt & 1;
        if (kt < 15) load_stage(kt + 1);

        const uint32_t* as = Abuf[cb];
        const uint32_t* bs = Bbuf[cb];
#pragma unroll
        for (int ks = 0; ks < 2; ks++) {
            const int kb = ks * 8;
            const int kw = kb + tig * 2;
            uint32_t a[2][4];
#pragma unroll
            for (int mi = 0; mi < 2; mi++) {
                const int r = wm + mi * 16 + gid;
                const uint2 lo = *(const uint2*)(as + r * APITCH + kw);
                const uint2 hi = *(const uint2*)(as + (r + 8) * APITCH + kw);
                a[mi][0] = lo.x; a[mi][1] = hi.x; a[mi][2] = lo.y; a[mi][3] = hi.y;
            }
#pragma unroll
            for (int nj = 0; nj < 8; nj++) {
                const int c = wn + nj * 8 + gid;
                const uint32_t b0 = bs[(kb + tig) * BPITCH + c];
                const uint32_t b1 = bs[(kb + 4 + tig) * BPITCH + c];
                mma_f16(acc[0][nj], a[0], b0, b1);
                mma_f16(acc[1][nj], a[1], b0, b1);
            }
        }

        if (kt < 15) stage(cb ^ 1);
        __syncthreads();
    }

#pragma unroll
    for (int mi = 0; mi < 2; mi++) {
#pragma unroll
        for (int nj = 0; nj < 8; nj++) {
            const int row = m0 + wm + mi * 16 + gid;
            const int col = n0 + wn + nj * 8 + tig * 2;
            const float2 bv = *(const float2*)(bias + col);
            *(float2*)(Cout + (size_t)row * 512 + col) =
                make_float2(acc[mi][nj][0] + bv.x, acc[mi][nj][1] + bv.y);
            *(float2*)(Cout + (size_t)(row + 8) * 512 + col) =
                make_float2(acc[mi][nj][2] + bv.x, acc[mi][nj][3] + bv.y);
        }
    }
}

// ---------------------------------------------------------------------------
// Attention (byte-identical to R14 pass): mma core, fp16 word-shuffle staging
// ---------------------------------------------------------------------------
#define QPITCH 40
#define KVPITCH 72

__global__ __launch_bounds__(128)
void attn_mma(const float* __restrict__ mask)
{
    __shared__ uint32_t sQ[64 * QPITCH];
    __shared__ uint32_t sK[32 * KVPITCH];
    __shared__ uint32_t sV[32 * KVPITCH];
    __shared__ float    sM[64 * 68];

    const int b = blockIdx.y;
    const int h = blockIdx.x;
    const int t = threadIdx.x;
    const size_t base = ((size_t)b * 64) * 512 + (size_t)h * 64;

    {
        const int row = t >> 1, ch = t & 1;
        const __half* src = g_q + base + (size_t)row * 512 + ch * 32;
        uint32_t* dq = sQ + row * QPITCH + ch * 16;
#pragma unroll
        for (int g = 0; g < 2; g++) {
            uint4 u0 = *(const uint4*)(src + g * 16);
            uint4 u1 = *(const uint4*)(src + g * 16 + 8);
            *(uint4*)(dq + g * 8)     = make_uint4(u0.x, u1.x, u0.y, u1.y);
            *(uint4*)(dq + g * 8 + 4) = make_uint4(u0.z, u1.z, u0.w, u1.w);
        }
    }
    {
        const int j = t >> 1, dh = (t & 1) * 32;
        const __half* src = g_k + base + (size_t)j * 512 + dh;
        uint32_t wds[16];
#pragma unroll
        for (int g = 0; g < 4; g++) *(uint4*)&wds[4 * g] = *(const uint4*)(src + 8 * g);
        const int kk0 = dh >> 1;
#pragma unroll
        for (int p = 0; p < 16; p++)
            sK[(kk0 + p) * KVPITCH + j] = wds[p];
    }
    {
        const int kk = t >> 2, nb = (t & 3) * 16;
        const __half* vlo = g_v + base + (size_t)(2 * kk) * 512 + nb;
        const __half* vhi = vlo + 512;
        uint32_t L[8], H[8];
        *(uint4*)&L[0] = *(const uint4*)(vlo);
        *(uint4*)&L[4] = *(const uint4*)(vlo + 8);
        *(uint4*)&H[0] = *(const uint4*)(vhi);
        *(uint4*)&H[4] = *(const uint4*)(vhi + 8);
        uint32_t* dv = sV + kk * KVPITCH + nb;
        uint32_t o[16];
#pragma unroll
        for (int j = 0; j < 8; j++) {
            o[2 * j]     = __byte_perm(L[j], H[j], 0x5410);
            o[2 * j + 1] = __byte_perm(L[j], H[j], 0x7632);
        }
#pragma unroll
        for (int g = 0; g < 4; g++) *(uint4*)(dv + 4 * g) = *(uint4*)&o[4 * g];
    }
    {
        const int row = t >> 1, cm = (t & 1) * 32;
        const float* src = mask + (size_t)b * 4096 + row * 64 + cm;
        float* dm = sM + row * 68 + cm;
#pragma unroll
        for (int g = 0; g < 8; g++) *(float4*)(dm + 4 * g) = *(const float4*)(src + 4 * g);
    }
    __syncthreads();

    const int wq = t >> 5, lane = t & 31;
    const int gid = lane >> 2, tig = lane & 3;
    const int r0 = wq * 16 + gid;

    float sacc[8][4];
#pragma unroll
    for (int nj = 0; nj < 8; nj++)
#pragma unroll
        for (int c = 0; c < 4; c++) sacc[nj][c] = 0.0f;

#pragma unroll
    for (int KS = 0; KS < 4; KS++) {
        const int kw = KS * 8 + tig * 2;
        const uint2 lo = *(const uint2*)(sQ + r0 * QPITCH + kw);
        const uint2 hi = *(const uint2*)(sQ + (r0 + 8) * QPITCH + kw);
        uint32_t a[4] = { lo.x, hi.x, lo.y, hi.y };
#pragma unroll
        for (int nj = 0; nj < 8; nj++) {
            const int c = nj * 8 + gid;
            const uint32_t b0 = sK[(KS * 8 + tig) * KVPITCH + c];
            const uint32_t b1 = sK[(KS * 8 + 4 + tig) * KVPITCH + c];
            mma_f16(sacc[nj], a, b0, b1);
        }
    }

    float mx0 = -1e30f, mx1 = -1e30f;
#pragma unroll
    for (int nj = 0; nj < 8; nj++) {
        const float2 m0 = *(const float2*)(sM + r0 * 68 + nj * 8 + 2 * tig);
        const float2 m1 = *(const float2*)(sM + (r0 + 8) * 68 + nj * 8 + 2 * tig);
        sacc[nj][0] = sacc[nj][0] * 0.125f + __logf(m0.x + 1e-9f);
        sacc[nj][1] = sacc[nj][1] * 0.125f + __logf(m0.y + 1e-9f);
        sacc[nj][2] = sacc[nj][2] * 0.125f + __logf(m1.x + 1e-9f);
        sacc[nj][3] = sacc[nj][3] * 0.125f + __logf(m1.y + 1e-9f);
        mx0 = fmaxf(mx0, fmaxf(sacc[nj][0], sacc[nj][1]));
        mx1 = fmaxf(mx1, fmaxf(sacc[nj][2], sacc[nj][3]));
    }
    mx0 = fmaxf(mx0, __shfl_xor_sync(0xffffffffu, mx0, 1));
    mx0 = fmaxf(mx0, __shfl_xor_sync(0xffffffffu, mx0, 2));
    mx1 = fmaxf(mx1, __shfl_xor_sync(0xffffffffu, mx1, 1));
    mx1 = fmaxf(mx1, __shfl_xor_sync(0xffffffffu, mx1, 2));

    float sum0 = 0.0f, sum1 = 0.0f;
#pragma unroll
    for (int nj = 0; nj < 8; nj++) {
        sacc[nj][0] = __expf(sacc[nj][0] - mx0);
        sacc[nj][1] = __expf(sacc[nj][1] - mx0);
        sacc[nj][2] = __expf(sacc[nj][2] - mx1);
        sacc[nj][3] = __expf(sacc[nj][3] - mx1);
        sum0 += sacc[nj][0] + sacc[nj][1];
        sum1 += sacc[nj][2] + sacc[nj][3];
    }
    sum0 += __shfl_xor_sync(0xffffffffu, sum0, 1);
    sum0 += __shfl_xor_sync(0xffffffffu, sum0, 2);
    sum1 += __shfl_xor_sync(0xffffffffu, sum1, 1);
    sum1 += __shfl_xor_sync(0xffffffffu, sum1, 2);
    const float inv0 = 1.0f / sum0, inv1 = 1.0f / sum1;
#pragma unroll
    for (int nj = 0; nj < 8; nj++) {
        sacc[nj][0] *= inv0; sacc[nj][1] *= inv0;
        sacc[nj][2] *= inv1; sacc[nj][3] *= inv1;
    }

    float oacc[8][4];
#pragma unroll
    for (int nd = 0; nd < 8; nd++)
#pragma unroll
        for (int c = 0; c < 4; c++) oacc[nd][c] = 0.0f;

#pragma unroll
    for (int JS = 0; JS < 4; JS++) {
        uint32_t a[4];
        a[0] = pack_h2(sacc[2 * JS][0],     sacc[2 * JS][1]);
        a[1] = pack_h2(sacc[2 * JS][2],     sacc[2 * JS][3]);
        a[2] = pack_h2(sacc[2 * JS + 1][0], sacc[2 * JS + 1][1]);
        a[3] = pack_h2(sacc[2 * JS + 1][2], sacc[2 * JS + 1][3]);
#pragma unroll
        for (int nd = 0; nd < 8; nd++) {
            const int c = nd * 8 + gid;
            const uint32_t b0 = sV[(JS * 8 + tig) * KVPITCH + c];
            const uint32_t b1 = sV[(JS * 8 + 4 + tig) * KVPITCH + c];
            mma_f16(oacc[nd], a, b0, b1);
        }
    }

    const int grow = b * 64 + r0;
#pragma unroll
    for (int nd = 0; nd < 8; nd++) {
        const int col = h * 64 + nd * 8 + tig * 2;
        *(uint32_t*)(g_att + (size_t)grow * 512 + col) =
            pack_h2(oacc[nd][0], oacc[nd][1]);
        *(uint32_t*)(g_att + (size_t)(grow + 8) * 512 + col) =
            pack_h2(oacc[nd][2], oacc[nd][3]);
    }
}

__global__ void tail_zero(float* __restrict__ out, long long start, long long total)
{
    long long i = start + (long long)blockIdx.x * blockDim.x + threadIdx.x;
    if (i < total) out[i] = 0.0f;
}

// ---------------------------------------------------------------------------
extern "C" void kernel_launch(void* const* d_in, const int* in_sizes, int n_in,
                              void* d_out, int out_size)
{
    const float* x    = (const float*)d_in[0];
    const float* mask = (const float*)d_in[1];
    const float* Wq   = (const float*)d_in[2];
    const float* bq   = (const float*)d_in[3];
    const float* Wk   = (const float*)d_in[4];
    const float* bk   = (const float*)d_in[5];
    const float* Wv   = (const float*)d_in[6];
    const float* bv   = (const float*)d_in[7];
    const float* Wo   = (const float*)d_in[8];
    const float* bo   = (const float*)d_in[9];
    float* out = (float*)d_out;

    cudaFuncSetAttribute(gemm_qkv,
                         cudaFuncAttributeMaxDynamicSharedMemorySize, GEMM_DSMEM);
    cudaFuncSetAttribute(gemm_out,
                         cudaFuncAttributeMaxDynamicSharedMemorySize, GEMM_DSMEM);

    // 0) Tail first (ccd_loss scalar / padding)
    long long tail = (long long)out_size - OUT_ELEMS;
    if (tail > 0) {
        int blocks = (int)((tail + 255) / 256);
        tail_zero<<<blocks, 256>>>(out, OUT_ELEMS, (long long)out_size);
    }

    // 1) Fused QKV projections (grid.x = 6 -> {q,k,v} x 2 n-tiles of 256)
    gemm_qkv<<<dim3(6, 1024), 512, GEMM_DSMEM>>>(x, Wq, Wk, Wv, bq, bk, bv);

    // 2) Channel-masked attention (tensor-core)
    attn_mma<<<dim3(HEADS, BATCH), 128>>>(mask);

    // 3) Output projection (grid.x = 2 n-tiles of 256)
    gemm_out<<<dim3(2, 1024), 512, GEMM_DSMEM>>>(out, Wo, bo);
}